// round 3
// baseline (speedup 1.0000x reference)
#include <cuda_runtime.h>

// Problem constants
#define B_DIM  32
#define S_DIM  2048
#define D_DIM  768
#define NL_DIM 512
#define NF_DIM 64

// Scratch: prefix sums (allocation-free rule -> __device__ globals)
__device__ float g_csum_tok[(size_t)B_DIM * (S_DIM + 1) * D_DIM];   // ~201 MB
__device__ float g_csum_line[(size_t)B_DIM * (NL_DIM + 1) * D_DIM]; // ~50 MB

// ---------------------------------------------------------------------------
// Kernel 1: C[M,N] = A[M,K] @ W[K,N] + bias,  M=B*S, N=K=D
// Classic SMEM-tiled SGEMM: 128x128 block tile, BK=8, 8x8 per-thread micro-tile
// ---------------------------------------------------------------------------
#define GBM 128
#define GBN 128
#define GBK 8
#define GTM 8
#define GTN 8

__global__ __launch_bounds__(256, 2) void gemm_bias_kernel(
    const float* __restrict__ A, const float* __restrict__ W,
    const float* __restrict__ bias, float* __restrict__ C) {
  const int K = D_DIM, N = D_DIM;
  __shared__ float As[GBK][GBM];
  __shared__ float Bs[GBK][GBN];

  const int tid = threadIdx.x;
  const int tx = tid & 15;   // 0..15 -> column group
  const int ty = tid >> 4;   // 0..15 -> row group
  const int brow = blockIdx.y * GBM;
  const int bcol = blockIdx.x * GBN;

  // A tile load mapping: 128x8 floats = 256 float4, one per thread
  const int a_row = tid >> 1;
  const int a_col = (tid & 1) * 4;
  // B tile load mapping: 8x128 floats = 256 float4, one per thread
  const int b_row = tid >> 5;
  const int b_col = (tid & 31) * 4;

  float acc[GTM][GTN];
#pragma unroll
  for (int i = 0; i < GTM; i++)
#pragma unroll
    for (int j = 0; j < GTN; j++) acc[i][j] = 0.0f;

  for (int k0 = 0; k0 < K; k0 += GBK) {
    float4 av = *(const float4*)(&A[(size_t)(brow + a_row) * K + k0 + a_col]);
    As[a_col + 0][a_row] = av.x;
    As[a_col + 1][a_row] = av.y;
    As[a_col + 2][a_row] = av.z;
    As[a_col + 3][a_row] = av.w;
    *(float4*)(&Bs[b_row][b_col]) =
        *(const float4*)(&W[(size_t)(k0 + b_row) * N + bcol + b_col]);
    __syncthreads();

#pragma unroll
    for (int k = 0; k < GBK; k++) {
      float af[GTM], bf[GTN];
#pragma unroll
      for (int i = 0; i < GTM; i++) af[i] = As[k][ty * GTM + i];
#pragma unroll
      for (int j = 0; j < GTN; j++) bf[j] = Bs[k][tx * GTN + j];
#pragma unroll
      for (int i = 0; i < GTM; i++)
#pragma unroll
        for (int j = 0; j < GTN; j++) acc[i][j] += af[i] * bf[j];
    }
    __syncthreads();
  }

#pragma unroll
  for (int i = 0; i < GTM; i++) {
    const int row = brow + ty * GTM + i;
#pragma unroll
    for (int j = 0; j < GTN; j += 4) {
      const int col = bcol + tx * GTN + j;
      float4 v;
      v.x = acc[i][j + 0] + bias[col + 0];
      v.y = acc[i][j + 1] + bias[col + 1];
      v.z = acc[i][j + 2] + bias[col + 2];
      v.w = acc[i][j + 3] + bias[col + 3];
      *(float4*)(&C[(size_t)row * N + col]) = v;
    }
  }
}

// ---------------------------------------------------------------------------
// Kernel 2/4: exclusive prefix sum along the sequence axis.
// One thread per (b, d) column; unroll-8 for MLP. Output has SEQ+1 rows.
// ---------------------------------------------------------------------------
template <int SEQ>
__global__ void cumsum_kernel(const float* __restrict__ x, float* __restrict__ csum) {
  const int idx = blockIdx.x * blockDim.x + threadIdx.x;  // b*D + d
  if (idx >= B_DIM * D_DIM) return;
  const int b = idx / D_DIM;
  const int d = idx - b * D_DIM;
  const float* xp = x + (size_t)b * SEQ * D_DIM + d;
  float* cp = csum + (size_t)b * (SEQ + 1) * D_DIM + d;
  float run = 0.0f;
  cp[0] = 0.0f;
  for (int s = 0; s < SEQ; s += 8) {
    float v[8];
#pragma unroll
    for (int u = 0; u < 8; u++) v[u] = xp[(size_t)(s + u) * D_DIM];
#pragma unroll
    for (int u = 0; u < 8; u++) {
      run += v[u];
      cp[(size_t)(s + 1 + u) * D_DIM] = run;
    }
  }
}

// ---------------------------------------------------------------------------
// Kernel 3/5: segment mean via prefix-sum gather.
// out[b, seg, d] = (csum[b, end, d] - csum[b, start, d]) / len  (0 if len<=0)
// ---------------------------------------------------------------------------
template <int NSEG, int SEQ>
__global__ void seg_mean_kernel(const float* __restrict__ csum,
                                const int* __restrict__ bounds,
                                float* __restrict__ out) {
  const int idx = blockIdx.x * blockDim.x + threadIdx.x;
  if (idx >= B_DIM * NSEG * D_DIM) return;
  const int d = idx % D_DIM;
  const int t = idx / D_DIM;
  const int seg = t % NSEG;
  const int b = t / NSEG;
  const int s0 = bounds[(b * NSEG + seg) * 2 + 0];
  const int s1 = bounds[(b * NSEG + seg) * 2 + 1];
  const float* cp = csum + (size_t)b * (SEQ + 1) * D_DIM + d;
  const int len = s1 - s0;
  float r = 0.0f;
  if (len > 0)
    r = (cp[(size_t)s1 * D_DIM] - cp[(size_t)s0 * D_DIM]) / (float)len;
  out[idx] = r;
}

// ---------------------------------------------------------------------------
// Kernel 6: file_emb[b, d] = mean over NF functions
// ---------------------------------------------------------------------------
__global__ void file_mean_kernel(const float* __restrict__ func,
                                 float* __restrict__ file) {
  const int idx = blockIdx.x * blockDim.x + threadIdx.x;
  if (idx >= B_DIM * D_DIM) return;
  const int b = idx / D_DIM;
  const int d = idx - b * D_DIM;
  const float* fp = func + (size_t)b * NF_DIM * D_DIM + d;
  float s = 0.0f;
#pragma unroll
  for (int f = 0; f < NF_DIM; f++) s += fp[(size_t)f * D_DIM];
  file[idx] = s * (1.0f / NF_DIM);
}

// ---------------------------------------------------------------------------
// Launch
// ---------------------------------------------------------------------------
extern "C" void kernel_launch(void* const* d_in, const int* in_sizes, int n_in,
                              void* d_out, int out_size) {
  const float* hidden = (const float*)d_in[0];  // [B, S, D]
  const float* W      = (const float*)d_in[1];  // [D, D]
  const float* bias   = (const float*)d_in[2];  // [D]
  const int*   lb     = (const int*)d_in[3];    // [B, NL, 2]
  const int*   fb     = (const int*)d_in[4];    // [B, NF, 2]

  float* out   = (float*)d_out;
  float* token = out;                                       // [B, S, D]
  float* line  = token + (size_t)B_DIM * S_DIM * D_DIM;     // [B, NL, D]
  float* func  = line + (size_t)B_DIM * NL_DIM * D_DIM;     // [B, NF, D]
  float* file  = func + (size_t)B_DIM * NF_DIM * D_DIM;     // [B, D]

  float* csum_tok;
  float* csum_line;
  cudaGetSymbolAddress((void**)&csum_tok, g_csum_tok);
  cudaGetSymbolAddress((void**)&csum_line, g_csum_line);

  // 1) token_emb = H @ W + b
  {
    dim3 grid(D_DIM / GBN, (B_DIM * S_DIM) / GBM);  // (6, 512)
    gemm_bias_kernel<<<grid, 256>>>(hidden, W, bias, token);
  }
  // 2) cumsum over S
  {
    int n = B_DIM * D_DIM;
    cumsum_kernel<S_DIM><<<(n + 255) / 256, 256>>>(token, csum_tok);
  }
  // 3) line segment means
  {
    int n = B_DIM * NL_DIM * D_DIM;
    seg_mean_kernel<NL_DIM, S_DIM><<<(n + 255) / 256, 256>>>(csum_tok, lb, line);
  }
  // 4) cumsum over NL
  {
    int n = B_DIM * D_DIM;
    cumsum_kernel<NL_DIM><<<(n + 255) / 256, 256>>>(line, csum_line);
  }
  // 5) function segment means
  {
    int n = B_DIM * NF_DIM * D_DIM;
    seg_mean_kernel<NF_DIM, NL_DIM><<<(n + 255) / 256, 256>>>(csum_line, fb, func);
  }
  // 6) file mean
  {
    int n = B_DIM * D_DIM;
    file_mean_kernel<<<(n + 255) / 256, 256>>>(func, file);
  }
}

// round 8
// speedup vs baseline: 1.6606x; 1.6606x over previous
#include <cuda_runtime.h>
#include <cuda_bf16.h>
#include <cstdint>

// Problem constants
#define B_DIM  32
#define S_DIM  2048
#define D_DIM  768
#define NL_DIM 512
#define NF_DIM 64

#define MTOT (B_DIM * S_DIM)      // 65536
#define KP   (3 * D_DIM)          // 2304 (concatenated split-K)

// ---------------------------------------------------------------------------
// Scratch (__device__ globals; allocation-free rule)
// ---------------------------------------------------------------------------
__device__ float g_csum_tok[(size_t)B_DIM * (S_DIM + 1) * D_DIM];   // ~201 MB
__device__ float g_csum_line[(size_t)B_DIM * (NL_DIM + 1) * D_DIM]; // ~50 MB
__device__ __align__(128) __nv_bfloat16 g_Abig[(size_t)MTOT * KP];  // ~302 MB
__device__ __align__(128) __nv_bfloat16 g_Bbig[(size_t)D_DIM * KP]; // ~3.5 MB

// ---------------------------------------------------------------------------
// PTX helpers (sm_80-portable only: cp.async, ldmatrix, mma.sync bf16)
// ---------------------------------------------------------------------------
__device__ __forceinline__ uint32_t smem_to_u32(const void* p) {
  uint32_t a;
  asm("{ .reg .u64 t; cvta.to.shared.u64 t, %1; cvt.u32.u64 %0, t; }"
      : "=r"(a) : "l"(p));
  return a;
}

__device__ __forceinline__ void cp16(uint32_t dst, const void* src) {
  asm volatile("cp.async.cg.shared.global [%0], [%1], 16;\n" ::"r"(dst),
               "l"(src));
}
#define CP_COMMIT() asm volatile("cp.async.commit_group;\n" ::: "memory")
#define CP_WAIT(n) asm volatile("cp.async.wait_group %0;\n" ::"n"(n) : "memory")

__device__ __forceinline__ void ldsm4(uint32_t* r, uint32_t addr) {
  asm volatile(
      "ldmatrix.sync.aligned.m8n8.x4.shared.b16 {%0,%1,%2,%3}, [%4];"
      : "=r"(r[0]), "=r"(r[1]), "=r"(r[2]), "=r"(r[3])
      : "r"(addr));
}

__device__ __forceinline__ void mma16816(float* c, const uint32_t* a,
                                         uint32_t b0, uint32_t b1) {
  asm volatile(
      "mma.sync.aligned.m16n8k16.row.col.f32.bf16.bf16.f32 "
      "{%0,%1,%2,%3}, {%4,%5,%6,%7}, {%8,%9}, {%0,%1,%2,%3};"
      : "+f"(c[0]), "+f"(c[1]), "+f"(c[2]), "+f"(c[3])
      : "r"(a[0]), "r"(a[1]), "r"(a[2]), "r"(a[3]), "r"(b0), "r"(b1));
}

// ---------------------------------------------------------------------------
// Kernel 0a: build A' = [Ahi | Alo | Ahi] rows, bf16, K' = 2304
// ---------------------------------------------------------------------------
__global__ void convert_a_kernel(const float* __restrict__ x,
                                 __nv_bfloat16* __restrict__ ap, int n4) {
  int i = blockIdx.x * blockDim.x + threadIdx.x;
  if (i >= n4) return;
  float4 v = ((const float4*)x)[i];
  __nv_bfloat16 h0 = __float2bfloat16(v.x);
  __nv_bfloat16 h1 = __float2bfloat16(v.y);
  __nv_bfloat16 h2 = __float2bfloat16(v.z);
  __nv_bfloat16 h3 = __float2bfloat16(v.w);
  __nv_bfloat16 l0 = __float2bfloat16(v.x - __bfloat162float(h0));
  __nv_bfloat16 l1 = __float2bfloat16(v.y - __bfloat162float(h1));
  __nv_bfloat16 l2 = __float2bfloat16(v.z - __bfloat162float(h2));
  __nv_bfloat16 l3 = __float2bfloat16(v.w - __bfloat162float(h3));
  int e0 = i * 4;
  int row = e0 / D_DIM;
  int col = e0 - row * D_DIM;
  __nv_bfloat162 hA = __halves2bfloat162(h0, h1);
  __nv_bfloat162 hB = __halves2bfloat162(h2, h3);
  __nv_bfloat162 lA = __halves2bfloat162(l0, l1);
  __nv_bfloat162 lB = __halves2bfloat162(l2, l3);
  __nv_bfloat162* base = (__nv_bfloat162*)(ap + (size_t)row * KP + col);
  base[0] = hA;  base[1] = hB;                               // slice 0: hi
  base[D_DIM / 2] = lA;  base[D_DIM / 2 + 1] = lB;           // slice 1: lo
  base[D_DIM] = hA;  base[D_DIM + 1] = hB;                   // slice 2: hi
}

// ---------------------------------------------------------------------------
// Kernel 0b: build B'[n][k'] = [Whi^T | Whi^T | Wlo^T]
// ---------------------------------------------------------------------------
__global__ void convert_w_kernel(const float* __restrict__ W,
                                 __nv_bfloat16* __restrict__ bp) {
  int idx = blockIdx.x * blockDim.x + threadIdx.x;
  if (idx >= D_DIM * D_DIM) return;
  int k = idx / D_DIM;
  int n = idx - k * D_DIM;
  float x = W[idx];
  __nv_bfloat16 h = __float2bfloat16(x);
  __nv_bfloat16 l = __float2bfloat16(x - __bfloat162float(h));
  __nv_bfloat16* row = bp + (size_t)n * KP;
  row[k] = h;
  row[D_DIM + k] = h;
  row[2 * D_DIM + k] = l;
}

// ---------------------------------------------------------------------------
// Kernel 1: bf16 mma.sync GEMM.  C[M=65536, N=768] = A'[M,K'] @ B'[N,K']^T + bias
// CTA 128x128, 4 warps (64x64 each), BK=32, 4-stage cp.async pipeline.
// SMEM rows padded to 80B -> conflict-free ldmatrix (r*20 mod 32 permutation).
// ---------------------------------------------------------------------------
#define BK 32
#define NITER (KP / BK)        // 72
#define ROWB 80                // smem bytes per 32-element bf16 row
#define STAGE_A (128 * ROWB)   // 10240
#define STAGE_BYTES (2 * STAGE_A)
#define NSTAGES 4
#define GEMM_SMEM (NSTAGES * STAGE_BYTES)  // 81920

__global__ __launch_bounds__(128, 2) void gemm_mma_kernel(
    const __nv_bfloat16* __restrict__ A, const __nv_bfloat16* __restrict__ Bm,
    const float* __restrict__ bias, float* __restrict__ C) {
  extern __shared__ char smem[];
  const uint32_t sbase = smem_to_u32(smem);
  const int tid = threadIdx.x;
  const int wid = tid >> 5;
  const int lane = tid & 31;
  const int wm = wid >> 1;     // 0..1 -> M half
  const int wn = wid & 1;      // 0..1 -> N half
  const int brow = blockIdx.y * 128;
  const int bcol = blockIdx.x * 128;

  // ldmatrix lane addressing: sub 0..3 selects (m-half, k-half) matrix
  const int sub = lane >> 3;
  const int rown = lane & 7;
  const int lrow = (sub & 1) * 8 + rown;       // row within 16-row tile
  const int lchunk = (sub >> 1) * 16;          // 16B chunk for k-half

  float acc[4][8][4];
#pragma unroll
  for (int i = 0; i < 4; i++)
#pragma unroll
    for (int j = 0; j < 8; j++)
#pragma unroll
      for (int q = 0; q < 4; q++) acc[i][j][q] = 0.0f;

  // stage loader: 128x32 bf16 A tile + 128x32 bf16 B tile, 16B per cp.async
#define LOAD_STAGE(s, k0)                                                     \
  do {                                                                        \
    uint32_t abase_ = sbase + (s) * STAGE_BYTES;                              \
    uint32_t bbase_ = abase_ + STAGE_A;                                       \
    _Pragma("unroll") for (int i_ = 0; i_ < 4; i_++) {                        \
      int lin_ = i_ * 128 + tid;                                              \
      int row_ = lin_ >> 2, c_ = lin_ & 3;                                    \
      cp16(abase_ + row_ * ROWB + c_ * 16,                                    \
           A + (size_t)(brow + row_) * KP + (k0) + c_ * 8);                   \
    }                                                                         \
    _Pragma("unroll") for (int i_ = 0; i_ < 4; i_++) {                        \
      int lin_ = i_ * 128 + tid;                                              \
      int row_ = lin_ >> 2, c_ = lin_ & 3;                                    \
      cp16(bbase_ + row_ * ROWB + c_ * 16,                                    \
           Bm + (size_t)(bcol + row_) * KP + (k0) + c_ * 8);                  \
    }                                                                         \
    CP_COMMIT();                                                              \
  } while (0)

  LOAD_STAGE(0, 0);
  LOAD_STAGE(1, BK);
  LOAD_STAGE(2, 2 * BK);

  for (int it = 0; it < NITER; ++it) {
    CP_WAIT(2);
    __syncthreads();
    // prefetch stage it+3 (its buffer was consumed in iter it-1)
    if (it + 3 < NITER) {
      LOAD_STAGE((it + 3) & 3, (it + 3) * BK);
    } else {
      CP_COMMIT();  // keep group count uniform
    }
    const uint32_t abase = sbase + (it & 3) * STAGE_BYTES;
    const uint32_t bbase = abase + STAGE_A;
#pragma unroll
    for (int ks = 0; ks < 2; ks++) {
      uint32_t af[4][4], bf[4][4];
#pragma unroll
      for (int mt = 0; mt < 4; mt++)
        ldsm4(af[mt],
              abase + (wm * 64 + mt * 16 + lrow) * ROWB + lchunk + ks * 32);
#pragma unroll
      for (int nt = 0; nt < 4; nt++)
        ldsm4(bf[nt],
              bbase + (wn * 64 + nt * 16 + lrow) * ROWB + lchunk + ks * 32);
#pragma unroll
      for (int mt = 0; mt < 4; mt++)
#pragma unroll
        for (int nt = 0; nt < 4; nt++) {
          mma16816(acc[mt][2 * nt + 0], af[mt], bf[nt][0], bf[nt][2]);
          mma16816(acc[mt][2 * nt + 1], af[mt], bf[nt][1], bf[nt][3]);
        }
    }
  }

  // Epilogue: direct float2 stores (4-lane groups cover full 32B sectors)
  const int gr = lane >> 2;
  const int gc2 = (lane & 3) * 2;
#pragma unroll
  for (int mt = 0; mt < 4; mt++) {
    const int r0 = brow + wm * 64 + mt * 16 + gr;
#pragma unroll
    for (int nt = 0; nt < 8; nt++) {
      const int col = bcol + wn * 64 + nt * 8 + gc2;
      const float b0 = __ldg(&bias[col]);
      const float b1 = __ldg(&bias[col + 1]);
      float2 v0 = make_float2(acc[mt][nt][0] + b0, acc[mt][nt][1] + b1);
      float2 v1 = make_float2(acc[mt][nt][2] + b0, acc[mt][nt][3] + b1);
      *(float2*)&C[(size_t)r0 * D_DIM + col] = v0;
      *(float2*)&C[(size_t)(r0 + 8) * D_DIM + col] = v1;
    }
  }
}

// ---------------------------------------------------------------------------
// Kernel 2/4: exclusive prefix sum along sequence axis (thread per (b,d))
// ---------------------------------------------------------------------------
template <int SEQ>
__global__ void cumsum_kernel(const float* __restrict__ x,
                              float* __restrict__ csum) {
  const int idx = blockIdx.x * blockDim.x + threadIdx.x;
  if (idx >= B_DIM * D_DIM) return;
  const int b = idx / D_DIM;
  const int d = idx - b * D_DIM;
  const float* xp = x + (size_t)b * SEQ * D_DIM + d;
  float* cp = csum + (size_t)b * (SEQ + 1) * D_DIM + d;
  float run = 0.0f;
  cp[0] = 0.0f;
  for (int s = 0; s < SEQ; s += 8) {
    float v[8];
#pragma unroll
    for (int u = 0; u < 8; u++) v[u] = xp[(size_t)(s + u) * D_DIM];
#pragma unroll
    for (int u = 0; u < 8; u++) {
      run += v[u];
      cp[(size_t)(s + 1 + u) * D_DIM] = run;
    }
  }
}

// ---------------------------------------------------------------------------
// Kernel 3/5: segment mean via prefix-sum gather
// ---------------------------------------------------------------------------
template <int NSEG, int SEQ>
__global__ void seg_mean_kernel(const float* __restrict__ csum,
                                const int* __restrict__ bounds,
                                float* __restrict__ out) {
  const int idx = blockIdx.x * blockDim.x + threadIdx.x;
  if (idx >= B_DIM * NSEG * D_DIM) return;
  const int d = idx % D_DIM;
  const int t = idx / D_DIM;
  const int seg = t % NSEG;
  const int b = t / NSEG;
  const int s0 = bounds[(b * NSEG + seg) * 2 + 0];
  const int s1 = bounds[(b * NSEG + seg) * 2 + 1];
  const float* cp = csum + (size_t)b * (SEQ + 1) * D_DIM + d;
  const int len = s1 - s0;
  float r = 0.0f;
  if (len > 0) r = (cp[(size_t)s1 * D_DIM] - cp[(size_t)s0 * D_DIM]) / (float)len;
  out[idx] = r;
}

// ---------------------------------------------------------------------------
// Kernel 6: file mean
// ---------------------------------------------------------------------------
__global__ void file_mean_kernel(const float* __restrict__ func,
                                 float* __restrict__ file) {
  const int idx = blockIdx.x * blockDim.x + threadIdx.x;
  if (idx >= B_DIM * D_DIM) return;
  const int b = idx / D_DIM;
  const int d = idx - b * D_DIM;
  const float* fp = func + (size_t)b * NF_DIM * D_DIM + d;
  float s = 0.0f;
#pragma unroll
  for (int f = 0; f < NF_DIM; f++) s += fp[(size_t)f * D_DIM];
  file[idx] = s * (1.0f / NF_DIM);
}

// ---------------------------------------------------------------------------
// Launch
// ---------------------------------------------------------------------------
extern "C" void kernel_launch(void* const* d_in, const int* in_sizes, int n_in,
                              void* d_out, int out_size) {
  const float* hidden = (const float*)d_in[0];  // [B, S, D]
  const float* W      = (const float*)d_in[1];  // [D, D]
  const float* bias   = (const float*)d_in[2];  // [D]
  const int*   lb     = (const int*)d_in[3];    // [B, NL, 2]
  const int*   fb     = (const int*)d_in[4];    // [B, NF, 2]

  float* out   = (float*)d_out;
  float* token = out;                                    // [B, S, D]
  float* line  = token + (size_t)B_DIM * S_DIM * D_DIM;  // [B, NL, D]
  float* func  = line + (size_t)B_DIM * NL_DIM * D_DIM;  // [B, NF, D]
  float* file  = func + (size_t)B_DIM * NF_DIM * D_DIM;  // [B, D]

  float* csum_tok;
  float* csum_line;
  __nv_bfloat16* abig;
  __nv_bfloat16* bbig;
  cudaGetSymbolAddress((void**)&csum_tok, g_csum_tok);
  cudaGetSymbolAddress((void**)&csum_line, g_csum_line);
  cudaGetSymbolAddress((void**)&abig, g_Abig);
  cudaGetSymbolAddress((void**)&bbig, g_Bbig);

  cudaFuncSetAttribute(gemm_mma_kernel,
                       cudaFuncAttributeMaxDynamicSharedMemorySize, GEMM_SMEM);

  // 0) split conversions into concatenated K' operands
  {
    int n4 = (MTOT * D_DIM) / 4;
    convert_a_kernel<<<(n4 + 255) / 256, 256>>>(hidden, abig, n4);
    int nw = D_DIM * D_DIM;
    convert_w_kernel<<<(nw + 255) / 256, 256>>>(W, bbig);
  }
  // 1) token = hidden @ W + bias  (bf16 mma.sync, 3-product split via K'=2304)
  {
    dim3 grid(D_DIM / 128, MTOT / 128);  // (6, 512)
    gemm_mma_kernel<<<grid, 128, GEMM_SMEM>>>(abig, bbig, bias, token);
  }
  // 2) cumsum over S
  {
    int n = B_DIM * D_DIM;
    cumsum_kernel<S_DIM><<<(n + 63) / 64, 64>>>(token, csum_tok);
  }
  // 3) line segment means
  {
    int n = B_DIM * NL_DIM * D_DIM;
    seg_mean_kernel<NL_DIM, S_DIM><<<(n + 255) / 256, 256>>>(csum_tok, lb, line);
  }
  // 4) cumsum over NL
  {
    int n = B_DIM * D_DIM;
    cumsum_kernel<NL_DIM><<<(n + 63) / 64, 64>>>(line, csum_line);
  }
  // 5) function segment means
  {
    int n = B_DIM * NF_DIM * D_DIM;
    seg_mean_kernel<NF_DIM, NL_DIM><<<(n + 255) / 256, 256>>>(csum_line, fb, func);
  }
  // 6) file mean
  {
    int n = B_DIM * D_DIM;
    file_mean_kernel<<<(n + 255) / 256, 256>>>(func, file);
  }
}

// round 9
// speedup vs baseline: 1.8595x; 1.1198x over previous
#include <cuda_runtime.h>
#include <cuda_bf16.h>
#include <cstdint>

// Problem constants
#define B_DIM  32
#define S_DIM  2048
#define D_DIM  768
#define NL_DIM 512
#define NF_DIM 64

#define MTOT (B_DIM * S_DIM)      // 65536
#define KP2  (2 * D_DIM)          // 1536: [hi | lo]

// ---------------------------------------------------------------------------
// Scratch (__device__ globals; allocation-free rule)
// ---------------------------------------------------------------------------
__device__ float g_csum_tok[(size_t)B_DIM * (S_DIM + 1) * D_DIM];   // ~201 MB
__device__ float g_csum_line[(size_t)B_DIM * (NL_DIM + 1) * D_DIM]; // ~50 MB
__device__ __align__(128) __nv_bfloat16 g_Abig[(size_t)MTOT * KP2]; // ~201 MB
__device__ __align__(128) __nv_bfloat16 g_Bbig[(size_t)D_DIM * KP2];
__device__ float g_part_tok[(size_t)B_DIM * 16 * D_DIM];   // chunk sums, S level
__device__ float g_part_line[(size_t)B_DIM * 8 * D_DIM];   // chunk sums, NL level

// ---------------------------------------------------------------------------
// PTX helpers (sm_80-portable: cp.async, ldmatrix, mma.sync bf16)
// ---------------------------------------------------------------------------
__device__ __forceinline__ uint32_t smem_to_u32(const void* p) {
  uint32_t a;
  asm("{ .reg .u64 t; cvta.to.shared.u64 t, %1; cvt.u32.u64 %0, t; }"
      : "=r"(a) : "l"(p));
  return a;
}

__device__ __forceinline__ void cp16(uint32_t dst, const void* src) {
  asm volatile("cp.async.cg.shared.global [%0], [%1], 16;\n" ::"r"(dst),
               "l"(src));
}
#define CP_COMMIT() asm volatile("cp.async.commit_group;\n" ::: "memory")
#define CP_WAIT(n) asm volatile("cp.async.wait_group %0;\n" ::"n"(n) : "memory")

__device__ __forceinline__ void ldsm4(uint32_t* r, uint32_t addr) {
  asm volatile(
      "ldmatrix.sync.aligned.m8n8.x4.shared.b16 {%0,%1,%2,%3}, [%4];"
      : "=r"(r[0]), "=r"(r[1]), "=r"(r[2]), "=r"(r[3])
      : "r"(addr));
}

__device__ __forceinline__ void mma16816(float* c, const uint32_t* a,
                                         uint32_t b0, uint32_t b1) {
  asm volatile(
      "mma.sync.aligned.m16n8k16.row.col.f32.bf16.bf16.f32 "
      "{%0,%1,%2,%3}, {%4,%5,%6,%7}, {%8,%9}, {%0,%1,%2,%3};"
      : "+f"(c[0]), "+f"(c[1]), "+f"(c[2]), "+f"(c[3])
      : "r"(a[0]), "r"(a[1]), "r"(a[2]), "r"(a[3]), "r"(b0), "r"(b1));
}

// ---------------------------------------------------------------------------
// Kernel 0a: A2 row = [Ahi(768) | Alo(768)], bf16
// ---------------------------------------------------------------------------
__global__ void convert_a_kernel(const float* __restrict__ x,
                                 __nv_bfloat16* __restrict__ ap, int n4) {
  int i = blockIdx.x * blockDim.x + threadIdx.x;
  if (i >= n4) return;
  float4 v = ((const float4*)x)[i];
  __nv_bfloat16 h0 = __float2bfloat16(v.x);
  __nv_bfloat16 h1 = __float2bfloat16(v.y);
  __nv_bfloat16 h2 = __float2bfloat16(v.z);
  __nv_bfloat16 h3 = __float2bfloat16(v.w);
  __nv_bfloat16 l0 = __float2bfloat16(v.x - __bfloat162float(h0));
  __nv_bfloat16 l1 = __float2bfloat16(v.y - __bfloat162float(h1));
  __nv_bfloat16 l2 = __float2bfloat16(v.z - __bfloat162float(h2));
  __nv_bfloat16 l3 = __float2bfloat16(v.w - __bfloat162float(h3));
  int e0 = i * 4;
  int row = e0 / D_DIM;
  int col = e0 - row * D_DIM;
  __nv_bfloat162* base = (__nv_bfloat162*)(ap + (size_t)row * KP2 + col);
  base[0] = __halves2bfloat162(h0, h1);
  base[1] = __halves2bfloat162(h2, h3);
  base[D_DIM / 2] = __halves2bfloat162(l0, l1);
  base[D_DIM / 2 + 1] = __halves2bfloat162(l2, l3);
}

// ---------------------------------------------------------------------------
// Kernel 0b: B2 row n = [Whi^T(768) | Wlo^T(768)]
// ---------------------------------------------------------------------------
__global__ void convert_w_kernel(const float* __restrict__ W,
                                 __nv_bfloat16* __restrict__ bp) {
  int idx = blockIdx.x * blockDim.x + threadIdx.x;
  if (idx >= D_DIM * D_DIM) return;
  int k = idx / D_DIM;
  int n = idx - k * D_DIM;
  float x = W[idx];
  __nv_bfloat16 h = __float2bfloat16(x);
  __nv_bfloat16 l = __float2bfloat16(x - __bfloat162float(h));
  __nv_bfloat16* row = bp + (size_t)n * KP2;
  row[k] = h;
  row[D_DIM + k] = l;
}

// ---------------------------------------------------------------------------
// Kernel 1: bf16 mma.sync split GEMM.  C = A@W + bias via hi*hi + hi*lo + lo*hi
// CTA 128x128, 256 thr (8 warps: 2M x 4N, warp tile 64x32), BK=32, K=768,
// 4 tiles/stage (Ahi, Alo, Bhi, Blo), 4-stage cp.async pipeline.
// SMEM rows padded to 80B -> conflict-free ldmatrix.
// ---------------------------------------------------------------------------
#define BK 32
#define NITER (D_DIM / BK)     // 24
#define ROWB 80
#define TILE_B (128 * ROWB)    // 10240 per tile
#define STAGE_BYTES (4 * TILE_B)  // 40960
#define NSTAGES 4
#define GEMM_SMEM (NSTAGES * STAGE_BYTES)  // 163840

#define T_AHI 0
#define T_ALO TILE_B
#define T_BHI (2 * TILE_B)
#define T_BLO (3 * TILE_B)

__global__ __launch_bounds__(256, 1) void gemm_mma_kernel(
    const __nv_bfloat16* __restrict__ A, const __nv_bfloat16* __restrict__ Bm,
    const float* __restrict__ bias, float* __restrict__ C) {
  extern __shared__ char smem[];
  const uint32_t sbase = smem_to_u32(smem);
  const int tid = threadIdx.x;
  const int wid = tid >> 5;
  const int lane = tid & 31;
  const int wm = wid >> 2;     // 0..1 -> 64-row M half
  const int wn = wid & 3;      // 0..3 -> 32-col N quarter
  const int brow = blockIdx.y * 128;
  const int bcol = blockIdx.x * 128;

  const int sub = lane >> 3;
  const int rown = lane & 7;
  const int lrow = (sub & 1) * 8 + rown;
  const int lchunk = (sub >> 1) * 16;

  float acc[4][4][4];
#pragma unroll
  for (int i = 0; i < 4; i++)
#pragma unroll
    for (int j = 0; j < 4; j++)
#pragma unroll
      for (int q = 0; q < 4; q++) acc[i][j][q] = 0.0f;

  // stage loader: 4 tiles of 128x32 bf16 (= 512 cp16 each), 2048 cp16 / 256 thr
#define LOAD_STAGE(s, k0)                                                     \
  do {                                                                        \
    uint32_t st_ = sbase + (s) * STAGE_BYTES;                                 \
    _Pragma("unroll") for (int i_ = 0; i_ < 2; i_++) {                        \
      int lin_ = i_ * 256 + tid;                                              \
      int row_ = lin_ >> 2, c_ = lin_ & 3;                                    \
      const __nv_bfloat16* ar_ = A + (size_t)(brow + row_) * KP2;             \
      cp16(st_ + T_AHI + row_ * ROWB + c_ * 16, ar_ + (k0) + c_ * 8);         \
      cp16(st_ + T_ALO + row_ * ROWB + c_ * 16, ar_ + D_DIM + (k0) + c_ * 8); \
      const __nv_bfloat16* br_ = Bm + (size_t)(bcol + row_) * KP2;            \
      cp16(st_ + T_BHI + row_ * ROWB + c_ * 16, br_ + (k0) + c_ * 8);         \
      cp16(st_ + T_BLO + row_ * ROWB + c_ * 16, br_ + D_DIM + (k0) + c_ * 8); \
    }                                                                         \
    CP_COMMIT();                                                              \
  } while (0)

  LOAD_STAGE(0, 0);
  LOAD_STAGE(1, BK);
  LOAD_STAGE(2, 2 * BK);

  for (int it = 0; it < NITER; ++it) {
    CP_WAIT(2);
    __syncthreads();
    if (it + 3 < NITER) {
      LOAD_STAGE((it + 3) & 3, (it + 3) * BK);
    } else {
      CP_COMMIT();  // keep group count uniform
    }
    const uint32_t st = sbase + (it & 3) * STAGE_BYTES;
#pragma unroll
    for (int ks = 0; ks < 2; ks++) {
      uint32_t ahi[4][4], alo[4][4], bhi[2][4], blo[2][4];
#pragma unroll
      for (int mt = 0; mt < 4; mt++) {
        uint32_t ra = (wm * 64 + mt * 16 + lrow) * ROWB + lchunk + ks * 32;
        ldsm4(ahi[mt], st + T_AHI + ra);
        ldsm4(alo[mt], st + T_ALO + ra);
      }
#pragma unroll
      for (int nt = 0; nt < 2; nt++) {
        uint32_t rb = (wn * 32 + nt * 16 + lrow) * ROWB + lchunk + ks * 32;
        ldsm4(bhi[nt], st + T_BHI + rb);
        ldsm4(blo[nt], st + T_BLO + rb);
      }
#pragma unroll
      for (int mt = 0; mt < 4; mt++)
#pragma unroll
        for (int nt = 0; nt < 2; nt++) {
          mma16816(acc[mt][2 * nt + 0], ahi[mt], bhi[nt][0], bhi[nt][2]);
          mma16816(acc[mt][2 * nt + 1], ahi[mt], bhi[nt][1], bhi[nt][3]);
          mma16816(acc[mt][2 * nt + 0], ahi[mt], blo[nt][0], blo[nt][2]);
          mma16816(acc[mt][2 * nt + 1], ahi[mt], blo[nt][1], blo[nt][3]);
          mma16816(acc[mt][2 * nt + 0], alo[mt], bhi[nt][0], bhi[nt][2]);
          mma16816(acc[mt][2 * nt + 1], alo[mt], bhi[nt][1], bhi[nt][3]);
        }
    }
  }

  // Epilogue: direct float2 stores
  const int gr = lane >> 2;
  const int gc2 = (lane & 3) * 2;
#pragma unroll
  for (int mt = 0; mt < 4; mt++) {
    const int r0 = brow + wm * 64 + mt * 16 + gr;
#pragma unroll
    for (int n8 = 0; n8 < 4; n8++) {
      const int col = bcol + wn * 32 + n8 * 8 + gc2;
      const float b0 = __ldg(&bias[col]);
      const float b1 = __ldg(&bias[col + 1]);
      float2 v0 = make_float2(acc[mt][n8][0] + b0, acc[mt][n8][1] + b1);
      float2 v1 = make_float2(acc[mt][n8][2] + b0, acc[mt][n8][3] + b1);
      *(float2*)&C[(size_t)r0 * D_DIM + col] = v0;
      *(float2*)&C[(size_t)(r0 + 8) * D_DIM + col] = v1;
    }
  }
}

// ---------------------------------------------------------------------------
// Kernels 2/4: two-pass chunked exclusive scan along the sequence axis.
// Pass 1: per-chunk sums.  Pass 2: seed from partial prefix, write scan.
// ---------------------------------------------------------------------------
template <int SEQ, int CH>
__global__ void cumsum_p1(const float* __restrict__ x,
                          float* __restrict__ part) {
  constexpr int NCH = SEQ / CH;
  const int idx = blockIdx.x * blockDim.x + threadIdx.x;
  if (idx >= B_DIM * NCH * D_DIM) return;
  const int d = idx % D_DIM;
  const int t = idx / D_DIM;
  const int c = t % NCH;
  const int b = t / NCH;
  const float* xp = x + ((size_t)b * SEQ + (size_t)c * CH) * D_DIM + d;
  float s = 0.0f;
  for (int r = 0; r < CH; r += 8) {
    float v[8];
#pragma unroll
    for (int u = 0; u < 8; u++) v[u] = xp[(size_t)(r + u) * D_DIM];
#pragma unroll
    for (int u = 0; u < 8; u++) s += v[u];
  }
  part[idx] = s;
}

template <int SEQ, int CH>
__global__ void cumsum_p2(const float* __restrict__ x,
                          const float* __restrict__ part,
                          float* __restrict__ csum) {
  constexpr int NCH = SEQ / CH;
  const int idx = blockIdx.x * blockDim.x + threadIdx.x;
  if (idx >= B_DIM * NCH * D_DIM) return;
  const int d = idx % D_DIM;
  const int t = idx / D_DIM;
  const int c = t % NCH;
  const int b = t / NCH;
  const float* pp = part + ((size_t)b * NCH) * D_DIM + d;
  float run = 0.0f;
  for (int i = 0; i < c; i++) run += pp[(size_t)i * D_DIM];
  const float* xp = x + ((size_t)b * SEQ + (size_t)c * CH) * D_DIM + d;
  float* cp = csum + ((size_t)b * (SEQ + 1) + (size_t)c * CH) * D_DIM + d;
  if (c == 0) cp[0] = 0.0f;
  for (int r = 0; r < CH; r += 8) {
    float v[8];
#pragma unroll
    for (int u = 0; u < 8; u++) v[u] = xp[(size_t)(r + u) * D_DIM];
#pragma unroll
    for (int u = 0; u < 8; u++) {
      run += v[u];
      cp[(size_t)(r + 1 + u) * D_DIM] = run;
    }
  }
}

// ---------------------------------------------------------------------------
// Kernel 3/5: segment mean via prefix-sum gather
// ---------------------------------------------------------------------------
template <int NSEG, int SEQ>
__global__ void seg_mean_kernel(const float* __restrict__ csum,
                                const int* __restrict__ bounds,
                                float* __restrict__ out) {
  const int idx = blockIdx.x * blockDim.x + threadIdx.x;
  if (idx >= B_DIM * NSEG * D_DIM) return;
  const int d = idx % D_DIM;
  const int t = idx / D_DIM;
  const int seg = t % NSEG;
  const int b = t / NSEG;
  const int s0 = bounds[(b * NSEG + seg) * 2 + 0];
  const int s1 = bounds[(b * NSEG + seg) * 2 + 1];
  const float* cp = csum + (size_t)b * (SEQ + 1) * D_DIM + d;
  const int len = s1 - s0;
  float r = 0.0f;
  if (len > 0) r = (cp[(size_t)s1 * D_DIM] - cp[(size_t)s0 * D_DIM]) / (float)len;
  out[idx] = r;
}

// ---------------------------------------------------------------------------
// Kernel 6: file mean
// ---------------------------------------------------------------------------
__global__ void file_mean_kernel(const float* __restrict__ func,
                                 float* __restrict__ file) {
  const int idx = blockIdx.x * blockDim.x + threadIdx.x;
  if (idx >= B_DIM * D_DIM) return;
  const int b = idx / D_DIM;
  const int d = idx - b * D_DIM;
  const float* fp = func + (size_t)b * NF_DIM * D_DIM + d;
  float s = 0.0f;
#pragma unroll
  for (int f = 0; f < NF_DIM; f++) s += fp[(size_t)f * D_DIM];
  file[idx] = s * (1.0f / NF_DIM);
}

// ---------------------------------------------------------------------------
// Launch
// ---------------------------------------------------------------------------
extern "C" void kernel_launch(void* const* d_in, const int* in_sizes, int n_in,
                              void* d_out, int out_size) {
  const float* hidden = (const float*)d_in[0];  // [B, S, D]
  const float* W      = (const float*)d_in[1];  // [D, D]
  const float* bias   = (const float*)d_in[2];  // [D]
  const int*   lb     = (const int*)d_in[3];    // [B, NL, 2]
  const int*   fb     = (const int*)d_in[4];    // [B, NF, 2]

  float* out   = (float*)d_out;
  float* token = out;                                    // [B, S, D]
  float* line  = token + (size_t)B_DIM * S_DIM * D_DIM;  // [B, NL, D]
  float* func  = line + (size_t)B_DIM * NL_DIM * D_DIM;  // [B, NF, D]
  float* file  = func + (size_t)B_DIM * NF_DIM * D_DIM;  // [B, D]

  float *csum_tok, *csum_line, *part_tok, *part_line;
  __nv_bfloat16 *abig, *bbig;
  cudaGetSymbolAddress((void**)&csum_tok, g_csum_tok);
  cudaGetSymbolAddress((void**)&csum_line, g_csum_line);
  cudaGetSymbolAddress((void**)&part_tok, g_part_tok);
  cudaGetSymbolAddress((void**)&part_line, g_part_line);
  cudaGetSymbolAddress((void**)&abig, g_Abig);
  cudaGetSymbolAddress((void**)&bbig, g_Bbig);

  cudaFuncSetAttribute(gemm_mma_kernel,
                       cudaFuncAttributeMaxDynamicSharedMemorySize, GEMM_SMEM);

  // 0) split conversions
  {
    int n4 = (MTOT * D_DIM) / 4;
    convert_a_kernel<<<(n4 + 255) / 256, 256>>>(hidden, abig, n4);
    int nw = D_DIM * D_DIM;
    convert_w_kernel<<<(nw + 255) / 256, 256>>>(W, bbig);
  }
  // 1) token = hidden @ W + bias (bf16 mma.sync, explicit 3-product)
  {
    dim3 grid(D_DIM / 128, MTOT / 128);  // (6, 512)
    gemm_mma_kernel<<<grid, 256, GEMM_SMEM>>>(abig, bbig, bias, token);
  }
  // 2) chunked scan over S
  {
    int n = B_DIM * 16 * D_DIM;
    cumsum_p1<S_DIM, 128><<<(n + 255) / 256, 256>>>(token, part_tok);
    cumsum_p2<S_DIM, 128><<<(n + 255) / 256, 256>>>(token, part_tok, csum_tok);
  }
  // 3) line segment means
  {
    int n = B_DIM * NL_DIM * D_DIM;
    seg_mean_kernel<NL_DIM, S_DIM><<<(n + 255) / 256, 256>>>(csum_tok, lb, line);
  }
  // 4) chunked scan over NL
  {
    int n = B_DIM * 8 * D_DIM;
    cumsum_p1<NL_DIM, 64><<<(n + 255) / 256, 256>>>(line, part_line);
    cumsum_p2<NL_DIM, 64><<<(n + 255) / 256, 256>>>(line, part_line, csum_line);
  }
  // 5) function segment means
  {
    int n = B_DIM * NF_DIM * D_DIM;
    seg_mean_kernel<NF_DIM, NL_DIM><<<(n + 255) / 256, 256>>>(csum_line, fb, func);
  }
  // 6) file mean
  {
    int n = B_DIM * D_DIM;
    file_mean_kernel<<<(n + 255) / 256, 256>>>(func, file);
  }
}

// round 10
// speedup vs baseline: 3.9410x; 2.1194x over previous
#include <cuda_runtime.h>
#include <cuda_fp16.h>
#include <cstdint>

// Problem constants
#define B_DIM  32
#define S_DIM  2048
#define D_DIM  768
#define NL_DIM 512
#define NF_DIM 64

#define MTOT (B_DIM * S_DIM)      // 65536

// Chunked-scan geometry
#define CH_S 128
#define NCH_S (S_DIM / CH_S)      // 16
#define CH_L 64
#define NCH_L (NL_DIM / CH_L)     // 8

// ---------------------------------------------------------------------------
// Scratch (__device__ globals; allocation-free rule)
// ---------------------------------------------------------------------------
__device__ float g_lc_tok[(size_t)B_DIM * S_DIM * D_DIM];    // ~201 MB local scans
__device__ float g_lc_line[(size_t)B_DIM * NL_DIM * D_DIM];  // ~50 MB
__device__ float g_pref_tok[(size_t)B_DIM * NCH_S * D_DIM];  // chunk prefixes
__device__ float g_pref_line[(size_t)B_DIM * NCH_L * D_DIM];
__device__ __align__(128) __half g_Ah[(size_t)MTOT * D_DIM];   // ~100 MB fp16
__device__ __align__(128) __half g_Wt[(size_t)D_DIM * D_DIM];  // W^T fp16

// ---------------------------------------------------------------------------
// PTX helpers (sm_80-portable: cp.async, ldmatrix, mma.sync f16)
// ---------------------------------------------------------------------------
__device__ __forceinline__ uint32_t smem_to_u32(const void* p) {
  uint32_t a;
  asm("{ .reg .u64 t; cvta.to.shared.u64 t, %1; cvt.u32.u64 %0, t; }"
      : "=r"(a) : "l"(p));
  return a;
}

__device__ __forceinline__ void cp16(uint32_t dst, const void* src) {
  asm volatile("cp.async.cg.shared.global [%0], [%1], 16;\n" ::"r"(dst),
               "l"(src));
}
#define CP_COMMIT() asm volatile("cp.async.commit_group;\n" ::: "memory")
#define CP_WAIT(n) asm volatile("cp.async.wait_group %0;\n" ::"n"(n) : "memory")

__device__ __forceinline__ void ldsm4(uint32_t* r, uint32_t addr) {
  asm volatile(
      "ldmatrix.sync.aligned.m8n8.x4.shared.b16 {%0,%1,%2,%3}, [%4];"
      : "=r"(r[0]), "=r"(r[1]), "=r"(r[2]), "=r"(r[3])
      : "r"(addr));
}

__device__ __forceinline__ void mma16816(float* c, const uint32_t* a,
                                         uint32_t b0, uint32_t b1) {
  asm volatile(
      "mma.sync.aligned.m16n8k16.row.col.f32.f16.f16.f32 "
      "{%0,%1,%2,%3}, {%4,%5,%6,%7}, {%8,%9}, {%0,%1,%2,%3};"
      : "+f"(c[0]), "+f"(c[1]), "+f"(c[2]), "+f"(c[3])
      : "r"(a[0]), "r"(a[1]), "r"(a[2]), "r"(a[3]), "r"(b0), "r"(b1));
}

// ---------------------------------------------------------------------------
// Kernel 0a: fp32 -> fp16 (A)
// ---------------------------------------------------------------------------
__global__ void convert_a_kernel(const float* __restrict__ x,
                                 __half* __restrict__ ah, int n4) {
  int i = blockIdx.x * blockDim.x + threadIdx.x;
  if (i >= n4) return;
  float4 v = ((const float4*)x)[i];
  __half2 h01 = __floats2half2_rn(v.x, v.y);
  __half2 h23 = __floats2half2_rn(v.z, v.w);
  ((__half2*)ah)[2 * i + 0] = h01;
  ((__half2*)ah)[2 * i + 1] = h23;
}

// ---------------------------------------------------------------------------
// Kernel 0b: W [K,N] -> W^T [N,K] fp16
// ---------------------------------------------------------------------------
__global__ void convert_w_kernel(const float* __restrict__ W,
                                 __half* __restrict__ wt) {
  int idx = blockIdx.x * blockDim.x + threadIdx.x;
  if (idx >= D_DIM * D_DIM) return;
  int k = idx / D_DIM;
  int n = idx - k * D_DIM;
  wt[(size_t)n * D_DIM + k] = __float2half_rn(W[idx]);
}

// ---------------------------------------------------------------------------
// Kernel 1: fp16 mma.sync GEMM.  C[M=65536, N=768] = A[M,K] @ Wt[N,K]^T + bias
// CTA 128x128, 4 warps (64x64 tiles), BK=32, 4-stage cp.async, occupancy 2.
// SMEM rows padded to 80B -> conflict-free ldmatrix.
// ---------------------------------------------------------------------------
#define BK 32
#define NITER (D_DIM / BK)     // 24
#define ROWB 80
#define TILE_B (128 * ROWB)    // 10240
#define STAGE_BYTES (2 * TILE_B)
#define NSTAGES 4
#define GEMM_SMEM (NSTAGES * STAGE_BYTES)  // 81920

__global__ __launch_bounds__(128, 2) void gemm_mma_kernel(
    const __half* __restrict__ A, const __half* __restrict__ Bm,
    const float* __restrict__ bias, float* __restrict__ C) {
  extern __shared__ char smem[];
  const uint32_t sbase = smem_to_u32(smem);
  const int tid = threadIdx.x;
  const int wid = tid >> 5;
  const int lane = tid & 31;
  const int wm = wid >> 1;     // 0..1 -> M half
  const int wn = wid & 1;      // 0..1 -> N half
  const int brow = blockIdx.y * 128;
  const int bcol = blockIdx.x * 128;

  const int sub = lane >> 3;
  const int rown = lane & 7;
  const int lrow = (sub & 1) * 8 + rown;
  const int lchunk = (sub >> 1) * 16;

  float acc[4][8][4];
#pragma unroll
  for (int i = 0; i < 4; i++)
#pragma unroll
    for (int j = 0; j < 8; j++)
#pragma unroll
      for (int q = 0; q < 4; q++) acc[i][j][q] = 0.0f;

  // stage loader: A tile 128x32 fp16 + B tile 128x32 fp16, 16B per cp.async
  // 1024 cp16 / 128 threads = 8 per thread
#define LOAD_STAGE(s, k0)                                                     \
  do {                                                                        \
    uint32_t abase_ = sbase + (s) * STAGE_BYTES;                              \
    uint32_t bbase_ = abase_ + TILE_B;                                        \
    _Pragma("unroll") for (int i_ = 0; i_ < 4; i_++) {                        \
      int lin_ = i_ * 128 + tid;                                              \
      int row_ = lin_ >> 2, c_ = lin_ & 3;                                    \
      cp16(abase_ + row_ * ROWB + c_ * 16,                                    \
           A + (size_t)(brow + row_) * D_DIM + (k0) + c_ * 8);                \
      cp16(bbase_ + row_ * ROWB + c_ * 16,                                    \
           Bm + (size_t)(bcol + row_) * D_DIM + (k0) + c_ * 8);               \
    }                                                                         \
    CP_COMMIT();                                                              \
  } while (0)

  LOAD_STAGE(0, 0);
  LOAD_STAGE(1, BK);
  LOAD_STAGE(2, 2 * BK);

  for (int it = 0; it < NITER; ++it) {
    CP_WAIT(2);
    __syncthreads();
    if (it + 3 < NITER) {
      LOAD_STAGE((it + 3) & 3, (it + 3) * BK);
    } else {
      CP_COMMIT();  // keep group count uniform
    }
    const uint32_t abase = sbase + (it & 3) * STAGE_BYTES;
    const uint32_t bbase = abase + TILE_B;
#pragma unroll
    for (int ks = 0; ks < 2; ks++) {
      uint32_t af[4][4], bf[4][4];
#pragma unroll
      for (int mt = 0; mt < 4; mt++)
        ldsm4(af[mt],
              abase + (wm * 64 + mt * 16 + lrow) * ROWB + lchunk + ks * 32);
#pragma unroll
      for (int nt = 0; nt < 4; nt++)
        ldsm4(bf[nt],
              bbase + (wn * 64 + nt * 16 + lrow) * ROWB + lchunk + ks * 32);
#pragma unroll
      for (int mt = 0; mt < 4; mt++)
#pragma unroll
        for (int nt = 0; nt < 4; nt++) {
          mma16816(acc[mt][2 * nt + 0], af[mt], bf[nt][0], bf[nt][2]);
          mma16816(acc[mt][2 * nt + 1], af[mt], bf[nt][1], bf[nt][3]);
        }
    }
  }

  // Epilogue: direct float2 stores
  const int gr = lane >> 2;
  const int gc2 = (lane & 3) * 2;
#pragma unroll
  for (int mt = 0; mt < 4; mt++) {
    const int r0 = brow + wm * 64 + mt * 16 + gr;
#pragma unroll
    for (int n8 = 0; n8 < 8; n8++) {
      const int col = bcol + wn * 64 + n8 * 8 + gc2;
      const float b0 = __ldg(&bias[col]);
      const float b1 = __ldg(&bias[col + 1]);
      float2 v0 = make_float2(acc[mt][n8][0] + b0, acc[mt][n8][1] + b1);
      float2 v1 = make_float2(acc[mt][n8][2] + b0, acc[mt][n8][3] + b1);
      *(float2*)&C[(size_t)r0 * D_DIM + col] = v0;
      *(float2*)&C[(size_t)(r0 + 8) * D_DIM + col] = v1;
    }
  }
}

// ---------------------------------------------------------------------------
// Kernel 2a/4a: per-chunk INCLUSIVE local scan + chunk sum.
// lc[b, s, d] = sum x[b, chunk_start..s, d];  part[b, c, d] = chunk total.
// ---------------------------------------------------------------------------
template <int SEQ, int CH>
__global__ void localscan_kernel(const float* __restrict__ x,
                                 float* __restrict__ lc,
                                 float* __restrict__ part) {
  constexpr int NCH = SEQ / CH;
  const int idx = blockIdx.x * blockDim.x + threadIdx.x;
  if (idx >= B_DIM * NCH * D_DIM) return;
  const int d = idx % D_DIM;
  const int t = idx / D_DIM;
  const int c = t % NCH;
  const int b = t / NCH;
  const size_t base = ((size_t)b * SEQ + (size_t)c * CH) * D_DIM + d;
  const float* xp = x + base;
  float* lp = lc + base;
  float run = 0.0f;
  for (int r = 0; r < CH; r += 8) {
    float v[8];
#pragma unroll
    for (int u = 0; u < 8; u++) v[u] = xp[(size_t)(r + u) * D_DIM];
#pragma unroll
    for (int u = 0; u < 8; u++) {
      run += v[u];
      lp[(size_t)(r + u) * D_DIM] = run;
    }
  }
  part[idx] = run;
}

// ---------------------------------------------------------------------------
// Kernel 2b/4b: in-place exclusive scan of chunk sums (NCH small).
// ---------------------------------------------------------------------------
template <int NCH>
__global__ void chunkpref_kernel(float* __restrict__ part) {
  const int idx = blockIdx.x * blockDim.x + threadIdx.x;
  if (idx >= B_DIM * D_DIM) return;
  const int b = idx / D_DIM;
  const int d = idx - b * D_DIM;
  float* pp = part + (size_t)b * NCH * D_DIM + d;
  float run = 0.0f;
#pragma unroll
  for (int c = 0; c < NCH; c++) {
    float v = pp[(size_t)c * D_DIM];
    pp[(size_t)c * D_DIM] = run;
    run += v;
  }
}

// ---------------------------------------------------------------------------
// Kernel 3/5: segment mean from local scans + chunk prefixes.
// csum(g) = g==0 ? 0 : pref[(g-1)/CH] + lc[g-1]
// ---------------------------------------------------------------------------
template <int NSEG, int SEQ, int CH>
__global__ void seg_mean_kernel(const float* __restrict__ lc,
                                const float* __restrict__ pref,
                                const int* __restrict__ bounds,
                                float* __restrict__ out) {
  constexpr int NCH = SEQ / CH;
  const int idx = blockIdx.x * blockDim.x + threadIdx.x;
  if (idx >= B_DIM * NSEG * D_DIM) return;
  const int d = idx % D_DIM;
  const int t = idx / D_DIM;
  const int seg = t % NSEG;
  const int b = t / NSEG;
  const int s0 = bounds[(b * NSEG + seg) * 2 + 0];
  const int s1 = bounds[(b * NSEG + seg) * 2 + 1];
  const int len = s1 - s0;
  float r = 0.0f;
  if (len > 0) {
    const float* lcb = lc + (size_t)b * SEQ * D_DIM + d;
    const float* pfb = pref + (size_t)b * NCH * D_DIM + d;
    float v1, v0;
    {
      int gm = s1 - 1;  // s1 >= 1 since len > 0
      v1 = pfb[(size_t)(gm / CH) * D_DIM] + lcb[(size_t)gm * D_DIM];
    }
    if (s0 == 0) {
      v0 = 0.0f;
    } else {
      int gm = s0 - 1;
      v0 = pfb[(size_t)(gm / CH) * D_DIM] + lcb[(size_t)gm * D_DIM];
    }
    r = (v1 - v0) / (float)len;
  }
  out[idx] = r;
}

// ---------------------------------------------------------------------------
// Kernel 6: file mean
// ---------------------------------------------------------------------------
__global__ void file_mean_kernel(const float* __restrict__ func,
                                 float* __restrict__ file) {
  const int idx = blockIdx.x * blockDim.x + threadIdx.x;
  if (idx >= B_DIM * D_DIM) return;
  const int b = idx / D_DIM;
  const int d = idx - b * D_DIM;
  const float* fp = func + (size_t)b * NF_DIM * D_DIM + d;
  float s = 0.0f;
#pragma unroll
  for (int f = 0; f < NF_DIM; f++) s += fp[(size_t)f * D_DIM];
  file[idx] = s * (1.0f / NF_DIM);
}

// ---------------------------------------------------------------------------
// Launch
// ---------------------------------------------------------------------------
extern "C" void kernel_launch(void* const* d_in, const int* in_sizes, int n_in,
                              void* d_out, int out_size) {
  const float* hidden = (const float*)d_in[0];  // [B, S, D]
  const float* W      = (const float*)d_in[1];  // [D, D]
  const float* bias   = (const float*)d_in[2];  // [D]
  const int*   lb     = (const int*)d_in[3];    // [B, NL, 2]
  const int*   fb     = (const int*)d_in[4];    // [B, NF, 2]

  float* out   = (float*)d_out;
  float* token = out;                                    // [B, S, D]
  float* line  = token + (size_t)B_DIM * S_DIM * D_DIM;  // [B, NL, D]
  float* func  = line + (size_t)B_DIM * NL_DIM * D_DIM;  // [B, NF, D]
  float* file  = func + (size_t)B_DIM * NF_DIM * D_DIM;  // [B, D]

  float *lc_tok, *lc_line, *pref_tok, *pref_line;
  __half *ah, *wt;
  cudaGetSymbolAddress((void**)&lc_tok, g_lc_tok);
  cudaGetSymbolAddress((void**)&lc_line, g_lc_line);
  cudaGetSymbolAddress((void**)&pref_tok, g_pref_tok);
  cudaGetSymbolAddress((void**)&pref_line, g_pref_line);
  cudaGetSymbolAddress((void**)&ah, g_Ah);
  cudaGetSymbolAddress((void**)&wt, g_Wt);

  cudaFuncSetAttribute(gemm_mma_kernel,
                       cudaFuncAttributeMaxDynamicSharedMemorySize, GEMM_SMEM);

  // 0) fp16 conversions
  {
    int n4 = (MTOT * D_DIM) / 4;
    convert_a_kernel<<<(n4 + 255) / 256, 256>>>(hidden, ah, n4);
    int nw = D_DIM * D_DIM;
    convert_w_kernel<<<(nw + 255) / 256, 256>>>(W, wt);
  }
  // 1) token = hidden @ W + bias (fp16 mma.sync, single product)
  {
    dim3 grid(D_DIM / 128, MTOT / 128);  // (6, 512)
    gemm_mma_kernel<<<grid, 128, GEMM_SMEM>>>(ah, wt, bias, token);
  }
  // 2) chunked local scan over S + chunk prefixes
  {
    int n = B_DIM * NCH_S * D_DIM;
    localscan_kernel<S_DIM, CH_S><<<(n + 255) / 256, 256>>>(token, lc_tok,
                                                            pref_tok);
    int m = B_DIM * D_DIM;
    chunkpref_kernel<NCH_S><<<(m + 255) / 256, 256>>>(pref_tok);
  }
  // 3) line segment means
  {
    int n = B_DIM * NL_DIM * D_DIM;
    seg_mean_kernel<NL_DIM, S_DIM, CH_S><<<(n + 255) / 256, 256>>>(
        lc_tok, pref_tok, lb, line);
  }
  // 4) chunked local scan over NL + chunk prefixes
  {
    int n = B_DIM * NCH_L * D_DIM;
    localscan_kernel<NL_DIM, CH_L><<<(n + 255) / 256, 256>>>(line, lc_line,
                                                             pref_line);
    int m = B_DIM * D_DIM;
    chunkpref_kernel<NCH_L><<<(m + 255) / 256, 256>>>(pref_line);
  }
  // 5) function segment means
  {
    int n = B_DIM * NF_DIM * D_DIM;
    seg_mean_kernel<NF_DIM, NL_DIM, CH_L><<<(n + 255) / 256, 256>>>(
        lc_line, pref_line, fb, func);
  }
  // 6) file mean
  {
    int n = B_DIM * D_DIM;
    file_mean_kernel<<<(n + 255) / 256, 256>>>(func, file);
  }
}